// round 16
// baseline (speedup 1.0000x reference)
#include <cuda_runtime.h>
#include <cuda_bf16.h>
#include <cuda_fp16.h>

#define NN   50000
#define EMB  128
#define HC   192      // HEADS*HID = 3*64
#define NE   800000

#define GEMM_BX 391                    // ceil(50000/128)
#define HIST_BLOCKS ((NE + 255) / 256)

// ---------------- scratch (device globals; no allocation allowed) ----------
__device__ __half g_xlh[(size_t)NN * HC];   // xl in fp16 (gather-side)
__device__ float  g_xr[(size_t)NN * HC];
__device__ int    g_cnt[NN];
__device__ int    g_off[NN];
__device__ int2   g_edge[NE];
__device__ float  g_scores[NN];

// ---------------- bf16 split helpers ----------------------------------------
__device__ __forceinline__ void split2(float x, float y, unsigned& h, unsigned& l) {
    __nv_bfloat162 hh = __floats2bfloat162_rn(x, y);
    float hx = __bfloat162float(hh.x), hy = __bfloat162float(hh.y);
    __nv_bfloat162 ll = __floats2bfloat162_rn(x - hx, y - hy);
    h = *reinterpret_cast<unsigned*>(&hh);
    l = *reinterpret_cast<unsigned*>(&ll);
}

#define MMA_BF16(d, a0, a1, a2, a3, b0, b1)                                    \
    asm volatile(                                                              \
        "mma.sync.aligned.m16n8k16.row.col.f32.bf16.bf16.f32 "                 \
        "{%0,%1,%2,%3}, {%4,%5,%6,%7}, {%8,%9}, {%0,%1,%2,%3};"                \
        : "+f"(d[0]), "+f"(d[1]), "+f"(d[2]), "+f"(d[3])                       \
        : "r"(a0), "r"(a1), "r"(a2), "r"(a3), "r"(b0), "r"(b1))

// ---------------- bf16-split HMMA GEMM (proven R10) --------------------------
#define PITCH 72
#define OFF_AH 0
#define OFF_AL (128 * PITCH * 2)
#define OFF_WH (2 * 128 * PITCH * 2)
#define OFF_WL (2 * 128 * PITCH * 2 + 192 * PITCH * 2)
#define SM_TOT (2 * 128 * PITCH * 2 + 2 * 192 * PITCH * 2)   // 92160 B

__global__ void __launch_bounds__(256) k_gemm_mma(
    const float* __restrict__ A,
    const float* __restrict__ Wl, const float* __restrict__ bl,
    const float* __restrict__ Wr, const float* __restrict__ br)
{
    extern __shared__ char sm[];
    __nv_bfloat16* AH = (__nv_bfloat16*)(sm + OFF_AH);
    __nv_bfloat16* AL = (__nv_bfloat16*)(sm + OFF_AL);
    __nv_bfloat16* WH = (__nv_bfloat16*)(sm + OFF_WH);
    __nv_bfloat16* WL = (__nv_bfloat16*)(sm + OFF_WL);

    int bz = blockIdx.y;
    const float* W    = bz ? Wr : Wl;
    const float* bias = bz ? br : bl;
    int row0 = blockIdx.x * 128;

    int tid  = threadIdx.x;
    int w    = tid >> 5;
    int lane = tid & 31;
    int g    = lane >> 2;
    int t    = lane & 3;
    int mw   = (w & 1) * 64;
    int nw   = (w >> 1) * 48;

    float acc[4][6][4];
    #pragma unroll
    for (int mf = 0; mf < 4; mf++)
        #pragma unroll
        for (int nf = 0; nf < 6; nf++)
            #pragma unroll
            for (int q = 0; q < 4; q++) acc[mf][nf][q] = 0.f;

    for (int kc = 0; kc < 2; kc++) {
        int k0f4 = kc * 16;
        __syncthreads();

        #pragma unroll
        for (int it = 0; it < 8; it++) {
            int idx = it * 256 + tid;
            int row = idx >> 4;
            int fq  = idx & 15;
            int gr  = row0 + row;
            if (gr >= NN) gr = NN - 1;
            float4 v = ((const float4*)A)[(size_t)gr * 32 + k0f4 + fq];
            unsigned h01, l01, h23, l23;
            split2(v.x, v.y, h01, l01);
            split2(v.z, v.w, h23, l23);
            int e = row * PITCH + fq * 4;
            *(uint2*)&AH[e] = make_uint2(h01, h23);
            *(uint2*)&AL[e] = make_uint2(l01, l23);
        }
        #pragma unroll
        for (int it = 0; it < 12; it++) {
            int idx = it * 256 + tid;
            int row = idx >> 4;
            int fq  = idx & 15;
            float4 v = ((const float4*)W)[(size_t)row * 32 + k0f4 + fq];
            unsigned h01, l01, h23, l23;
            split2(v.x, v.y, h01, l01);
            split2(v.z, v.w, h23, l23);
            int e = row * PITCH + fq * 4;
            *(uint2*)&WH[e] = make_uint2(h01, h23);
            *(uint2*)&WL[e] = make_uint2(l01, l23);
        }
        __syncthreads();

        #pragma unroll
        for (int ks = 0; ks < 4; ks++) {
            int kk = ks * 16;
            unsigned ah[4][4], al[4][4], bh[6][2], blo[6][2];
            #pragma unroll
            for (int mf = 0; mf < 4; mf++) {
                int r = mw + mf * 16 + g;
                int e0 = r * PITCH + kk + 2 * t;
                int e1 = (r + 8) * PITCH + kk + 2 * t;
                ah[mf][0] = *(const unsigned*)&AH[e0];
                ah[mf][1] = *(const unsigned*)&AH[e1];
                ah[mf][2] = *(const unsigned*)&AH[e0 + 8];
                ah[mf][3] = *(const unsigned*)&AH[e1 + 8];
                al[mf][0] = *(const unsigned*)&AL[e0];
                al[mf][1] = *(const unsigned*)&AL[e1];
                al[mf][2] = *(const unsigned*)&AL[e0 + 8];
                al[mf][3] = *(const unsigned*)&AL[e1 + 8];
            }
            #pragma unroll
            for (int nf = 0; nf < 6; nf++) {
                int c = nw + nf * 8 + g;
                int e = c * PITCH + kk + 2 * t;
                bh[nf][0]  = *(const unsigned*)&WH[e];
                bh[nf][1]  = *(const unsigned*)&WH[e + 8];
                blo[nf][0] = *(const unsigned*)&WL[e];
                blo[nf][1] = *(const unsigned*)&WL[e + 8];
            }
            #pragma unroll
            for (int mf = 0; mf < 4; mf++)
                #pragma unroll
                for (int nf = 0; nf < 6; nf++) {
                    MMA_BF16(acc[mf][nf], ah[mf][0], ah[mf][1], ah[mf][2], ah[mf][3],
                             bh[nf][0], bh[nf][1]);
                    MMA_BF16(acc[mf][nf], ah[mf][0], ah[mf][1], ah[mf][2], ah[mf][3],
                             blo[nf][0], blo[nf][1]);
                    MMA_BF16(acc[mf][nf], al[mf][0], al[mf][1], al[mf][2], al[mf][3],
                             bh[nf][0], bh[nf][1]);
                }
        }
    }

    #pragma unroll
    for (int mf = 0; mf < 4; mf++) {
        int r0 = row0 + mw + mf * 16 + g;
        #pragma unroll
        for (int nf = 0; nf < 6; nf++) {
            int col = nw + nf * 8 + 2 * t;
            float b0 = __ldg(&bias[col]), b1 = __ldg(&bias[col + 1]);
            float* d = acc[mf][nf];
            if (bz) {
                if (r0 < NN)
                    *(float2*)&g_xr[(size_t)r0 * HC + col] = make_float2(d[0] + b0, d[1] + b1);
                if (r0 + 8 < NN)
                    *(float2*)&g_xr[(size_t)(r0 + 8) * HC + col] = make_float2(d[2] + b0, d[3] + b1);
            } else {
                if (r0 < NN)
                    *(__half2*)&g_xlh[(size_t)r0 * HC + col] = __floats2half2_rn(d[0] + b0, d[1] + b1);
                if (r0 + 8 < NN)
                    *(__half2*)&g_xlh[(size_t)(r0 + 8) * HC + col] = __floats2half2_rn(d[2] + b0, d[3] + b1);
            }
        }
    }
}

// ---------------- histogram -------------------------------------------------
__global__ void k_hist(const int* __restrict__ ei) {
    int e = blockIdx.x * blockDim.x + threadIdx.x;
    if (e < NE) atomicAdd(&g_cnt[ei[NE + e]], 1);
}

// ---------------- x4-vectorized exclusive scan (single block) --------------
__global__ void k_scan() {
    __shared__ int wsum[32];
    __shared__ int carry;
    int tid  = threadIdx.x;
    int lane = tid & 31;
    int wid  = tid >> 5;
    if (tid == 0) carry = 0;
    __syncthreads();

    for (int base = 0; base < NN; base += 4096) {
        int idx = base + tid * 4;
        int4 v = make_int4(0, 0, 0, 0);
        if (idx < NN) v = *(const int4*)&g_cnt[idx];
        int t0 = v.x;
        int t1 = t0 + v.y;
        int t2 = t1 + v.z;
        int t3 = t2 + v.w;
        int x = t3;
        #pragma unroll
        for (int o = 1; o < 32; o <<= 1) {
            int t = __shfl_up_sync(0xffffffffu, x, o);
            if (lane >= o) x += t;
        }
        if (lane == 31) wsum[wid] = x;
        __syncthreads();
        if (wid == 0) {
            int s = wsum[lane];
            #pragma unroll
            for (int o = 1; o < 32; o <<= 1) {
                int t = __shfl_up_sync(0xffffffffu, s, o);
                if (lane >= o) s += t;
            }
            wsum[lane] = s;
        }
        __syncthreads();
        int c = carry;
        int b = (wid > 0 ? wsum[wid - 1] : 0) + c + x - t3;
        if (idx < NN)
            *(int4*)&g_off[idx] = make_int4(b, b + t0, b + t1, b + t2);
        __syncthreads();
        if (tid == 0) carry = c + wsum[31];
        __syncthreads();
    }
}

// ---------------- scatter ----------------------------------------------------
__global__ void k_scatter(const int* __restrict__ ei, const float* __restrict__ ea) {
    int e = blockIdx.x * blockDim.x + threadIdx.x;
    if (e >= NE) return;
    int s = ei[e];
    int d = ei[NE + e];
    int p = atomicAdd(&g_off[d], 1);
    g_edge[p] = make_int2(s, __float_as_int(ea[e]));
}

// ---------------- warp-per-node aggregation: ILP-2 shuffle chains -----------
// lane (grp=l>>4, p=l&15) holds channels 64h + 4p..4p+3 per head h.
// each group processes TWO of its edges per iteration (independent shfl-reduce
// chains interleave -> 26-cyc shuffle latency of chain A hidden by chain B).
// edge recs fetched 2 pairs ahead, fp16 gathers 1 pair ahead.
__global__ void __launch_bounds__(128) k_agg(
    const float* __restrict__ We, const float* __restrict__ att,
    const float* __restrict__ bias, const float* __restrict__ Wout,
    const float* __restrict__ bout)
{
    int n = (blockIdx.x * blockDim.x + threadIdx.x) >> 5;
    int l = threadIdx.x & 31;
    if (n >= NN) return;
    int grp = l >> 4, p = l & 15;

    int end = g_off[n];
    int beg = (n > 0) ? g_off[n - 1] : 0;

    const float LOG2E = 1.44269504088896f;
    float4 xi[3], av[3], wv[3];
    {
        const float* xrp = &g_xr[(size_t)n * HC + 4 * p];
        #pragma unroll
        for (int h = 0; h < 3; h++) {
            xi[h] = *(const float4*)(xrp + 64 * h);
            float4 a = *(const float4*)&att[64 * h + 4 * p];
            av[h] = make_float4(a.x * LOG2E, a.y * LOG2E, a.z * LOG2E, a.w * LOG2E);
            wv[h] = *(const float4*)&We[64 * h + 4 * p];
        }
    }

    float  rsum[3] = {0.f, 0.f, 0.f};
    float4 acc[3]  = {{0,0,0,0}, {0,0,0,0}, {0,0,0,0}};

// per-edge channel math: fe + fp16 data (3x uint2) -> s0,s1,s2 (pre-reduce)
#define EDGE_S(FE, U0, U1, U2, S0, S1, S2) do {                                \
    float2 c0, c1; float4 x0, x1, x2;                                          \
    c0 = __half22float2(*(__half2*)&(U0).x);                                   \
    c1 = __half22float2(*(__half2*)&(U0).y);                                   \
    x0 = make_float4(c0.x, c0.y, c1.x, c1.y);                                  \
    c0 = __half22float2(*(__half2*)&(U1).x);                                   \
    c1 = __half22float2(*(__half2*)&(U1).y);                                   \
    x1 = make_float4(c0.x, c0.y, c1.x, c1.y);                                  \
    c0 = __half22float2(*(__half2*)&(U2).x);                                   \
    c1 = __half22float2(*(__half2*)&(U2).y);                                   \
    x2 = make_float4(c0.x, c0.y, c1.x, c1.y);                                  \
    float mx, my, mz, mw_, sm, sa;                                             \
    mx  = fmaf(FE, wv[0].x, xi[0].x) + x0.x;                                   \
    my  = fmaf(FE, wv[0].y, xi[0].y) + x0.y;                                   \
    mz  = fmaf(FE, wv[0].z, xi[0].z) + x0.z;                                   \
    mw_ = fmaf(FE, wv[0].w, xi[0].w) + x0.w;                                   \
    sm = av[0].x * mx;               sa = av[0].x * fabsf(mx);                 \
    sm = fmaf(av[0].y, my,  sm);     sa = fmaf(av[0].y, fabsf(my),  sa);       \
    sm = fmaf(av[0].z, mz,  sm);     sa = fmaf(av[0].z, fabsf(mz),  sa);       \
    sm = fmaf(av[0].w, mw_, sm);     sa = fmaf(av[0].w, fabsf(mw_), sa);       \
    S0 = fmaf(0.6f, sm, 0.4f * sa);                                            \
    mx  = fmaf(FE, wv[1].x, xi[1].x) + x1.x;                                   \
    my  = fmaf(FE, wv[1].y, xi[1].y) + x1.y;                                   \
    mz  = fmaf(FE, wv[1].z, xi[1].z) + x1.z;                                   \
    mw_ = fmaf(FE, wv[1].w, xi[1].w) + x1.w;                                   \
    sm = av[1].x * mx;               sa = av[1].x * fabsf(mx);                 \
    sm = fmaf(av[1].y, my,  sm);     sa = fmaf(av[1].y, fabsf(my),  sa);       \
    sm = fmaf(av[1].z, mz,  sm);     sa = fmaf(av[1].z, fabsf(mz),  sa);       \
    sm = fmaf(av[1].w, mw_, sm);     sa = fmaf(av[1].w, fabsf(mw_), sa);       \
    S1 = fmaf(0.6f, sm, 0.4f * sa);                                            \
    mx  = fmaf(FE, wv[2].x, xi[2].x) + x2.x;                                   \
    my  = fmaf(FE, wv[2].y, xi[2].y) + x2.y;                                   \
    mz  = fmaf(FE, wv[2].z, xi[2].z) + x2.z;                                   \
    mw_ = fmaf(FE, wv[2].w, xi[2].w) + x2.w;                                   \
    sm = av[2].x * mx;               sa = av[2].x * fabsf(mx);                 \
    sm = fmaf(av[2].y, my,  sm);     sa = fmaf(av[2].y, fabsf(my),  sa);       \
    sm = fmaf(av[2].z, mz,  sm);     sa = fmaf(av[2].z, fabsf(mz),  sa);       \
    sm = fmaf(av[2].w, mw_, sm);     sa = fmaf(av[2].w, fabsf(mw_), sa);       \
    S2 = fmaf(0.6f, sm, 0.4f * sa);                                            \
} while (0)

// accumulate edge (weight W per head, fp16 data) into rsum/acc
#define EDGE_ACC(W0, W1, W2, U0, U1, U2) do {                                  \
    float2 c0, c1;                                                             \
    rsum[0] += (W0); rsum[1] += (W1); rsum[2] += (W2);                         \
    c0 = __half22float2(*(__half2*)&(U0).x);                                   \
    c1 = __half22float2(*(__half2*)&(U0).y);                                   \
    acc[0].x = fmaf(W0, c0.x, acc[0].x); acc[0].y = fmaf(W0, c0.y, acc[0].y);  \
    acc[0].z = fmaf(W0, c1.x, acc[0].z); acc[0].w = fmaf(W0, c1.y, acc[0].w);  \
    c0 = __half22float2(*(__half2*)&(U1).x);                                   \
    c1 = __half22float2(*(__half2*)&(U1).y);                                   \
    acc[1].x = fmaf(W1, c0.x, acc[1].x); acc[1].y = fmaf(W1, c0.y, acc[1].y);  \
    acc[1].z = fmaf(W1, c1.x, acc[1].z); acc[1].w = fmaf(W1, c1.y, acc[1].w);  \
    c0 = __half22float2(*(__half2*)&(U2).x);                                   \
    c1 = __half22float2(*(__half2*)&(U2).y);                                   \
    acc[2].x = fmaf(W2, c0.x, acc[2].x); acc[2].y = fmaf(W2, c0.y, acc[2].y);  \
    acc[2].z = fmaf(W2, c1.x, acc[2].z); acc[2].w = fmaf(W2, c1.y, acc[2].w);  \
} while (0)

#define GATHER(U0, U1, U2, SRC) do {                                           \
    const __half* bp = &g_xlh[(size_t)(SRC) * HC + 4 * p];                     \
    U0 = *(const uint2*)(bp);                                                  \
    U1 = *(const uint2*)(bp + 64);                                             \
    U2 = *(const uint2*)(bp + 128);                                            \
} while (0)

    if (end > beg) {
        int i0  = beg + grp;
        int lim = end - 1;
#define CLMP(I) (((I) < end) ? (I) : lim)
        // current pair recs + next pair recs
        int2 eA0 = g_edge[CLMP(i0)];
        int2 eB0 = g_edge[CLMP(i0 + 2)];
        int2 eA1 = g_edge[CLMP(i0 + 4)];
        int2 eB1 = g_edge[CLMP(i0 + 6)];
        uint2 cA0, cA1, cA2, cB0, cB1, cB2;      // current pair data
        GATHER(cA0, cA1, cA2, eA0.x);
        GATHER(cB0, cB1, cB2, eB0.x);

        int cnt0  = (end - beg + 1) >> 1;        // group-0 edge count (max)
        int niter = (cnt0 + 1) >> 1;             // pairs
        for (int it = 0; it < niter; it++) {
            int i = i0 + 4 * it;
            // recs for pair it+2
            int2 eA2 = g_edge[CLMP(i + 8)];
            int2 eB2 = g_edge[CLMP(i + 10)];
            // gathers for pair it+1
            uint2 nA0, nA1, nA2, nB0, nB1, nB2;
            GATHER(nA0, nA1, nA2, eA1.x);
            GATHER(nB0, nB1, nB2, eB1.x);

            // two independent logit chains
            float feA = __int_as_float(eA0.y);
            float feB = __int_as_float(eB0.y);
            float sA0, sA1, sA2, sB0, sB1, sB2;
            EDGE_S(feA, cA0, cA1, cA2, sA0, sA1, sA2);
            EDGE_S(feB, cB0, cB1, cB2, sB0, sB1, sB2);
            #pragma unroll
            for (int o = 8; o > 0; o >>= 1) {
                sA0 += __shfl_xor_sync(0xffffffffu, sA0, o);
                sB0 += __shfl_xor_sync(0xffffffffu, sB0, o);
                sA1 += __shfl_xor_sync(0xffffffffu, sA1, o);
                sB1 += __shfl_xor_sync(0xffffffffu, sB1, o);
                sA2 += __shfl_xor_sync(0xffffffffu, sA2, o);
                sB2 += __shfl_xor_sync(0xffffffffu, sB2, o);
            }
            bool vA = (i < end);
            bool vB = (i + 2 < end);
            float wA0 = vA ? exp2f(sA0) : 0.f;
            float wB0 = vB ? exp2f(sB0) : 0.f;
            float wA1 = vA ? exp2f(sA1) : 0.f;
            float wB1 = vB ? exp2f(sB1) : 0.f;
            float wA2 = vA ? exp2f(sA2) : 0.f;
            float wB2 = vB ? exp2f(sB2) : 0.f;
            EDGE_ACC(wA0, wA1, wA2, cA0, cA1, cA2);
            EDGE_ACC(wB0, wB1, wB2, cB0, cB1, cB2);

            // rotate pipeline
            eA0 = eA1; eB0 = eB1; eA1 = eA2; eB1 = eB2;
            cA0 = nA0; cA1 = nA1; cA2 = nA2;
            cB0 = nB0; cB1 = nB1; cB2 = nB2;
        }
#undef CLMP

        // combine the two groups (same channels at l and l^16)
        #pragma unroll
        for (int h = 0; h < 3; h++) {
            rsum[h] += __shfl_xor_sync(0xffffffffu, rsum[h], 16);
            acc[h].x += __shfl_xor_sync(0xffffffffu, acc[h].x, 16);
            acc[h].y += __shfl_xor_sync(0xffffffffu, acc[h].y, 16);
            acc[h].z += __shfl_xor_sync(0xffffffffu, acc[h].z, 16);
            acc[h].w += __shfl_xor_sync(0xffffffffu, acc[h].w, 16);
        }
    }

    float4 o = make_float4(0.f, 0.f, 0.f, 0.f);
    if (end > beg) {
        float r0 = 1.f / rsum[0], r1 = 1.f / rsum[1], r2 = 1.f / rsum[2];
        o.x = (acc[0].x * r0 + acc[1].x * r1 + acc[2].x * r2) * (1.f / 3.f);
        o.y = (acc[0].y * r0 + acc[1].y * r1 + acc[2].y * r2) * (1.f / 3.f);
        o.z = (acc[0].z * r0 + acc[1].z * r1 + acc[2].z * r2) * (1.f / 3.f);
        o.w = (acc[0].w * r0 + acc[1].w * r1 + acc[2].w * r2) * (1.f / 3.f);
    }
    float4 bia = *(const float4*)&bias[4 * p];
    float4 wo  = *(const float4*)&Wout[4 * p];
    o.x += bia.x; o.y += bia.y; o.z += bia.z; o.w += bia.w;

    float sp = o.x * wo.x + o.y * wo.y + o.z * wo.z + o.w * wo.w;
    #pragma unroll
    for (int off = 8; off > 0; off >>= 1)
        sp += __shfl_xor_sync(0xffffffffu, sp, off);
    if (l == 0) g_scores[n] = sp + bout[0];
}

// ---------------- global softmax over 50k scores ---------------------------
__global__ void k_softmax(float* __restrict__ out) {
    __shared__ float redm[32];
    __shared__ float reds[32];
    int tid = threadIdx.x;

    float mx = -1e30f;
    for (int i = tid; i < NN; i += 1024) mx = fmaxf(mx, g_scores[i]);
    #pragma unroll
    for (int o = 16; o > 0; o >>= 1) mx = fmaxf(mx, __shfl_xor_sync(0xffffffffu, mx, o));
    if ((tid & 31) == 0) redm[tid >> 5] = mx;
    __syncthreads();
    if (tid < 32) {
        float v = redm[tid];
        #pragma unroll
        for (int o = 16; o > 0; o >>= 1) v = fmaxf(v, __shfl_xor_sync(0xffffffffu, v, o));
        redm[tid] = v;
    }
    __syncthreads();
    mx = redm[0];

    float sm = 0.f;
    for (int i = tid; i < NN; i += 1024) {
        float e = __expf(g_scores[i] - mx);
        out[i] = e;
        sm += e;
    }
    #pragma unroll
    for (int o = 16; o > 0; o >>= 1) sm += __shfl_xor_sync(0xffffffffu, sm, o);
    if ((tid & 31) == 0) reds[tid >> 5] = sm;
    __syncthreads();
    if (tid < 32) {
        float v = reds[tid];
        #pragma unroll
        for (int o = 16; o > 0; o >>= 1) v += __shfl_xor_sync(0xffffffffu, v, o);
        reds[tid] = v;
    }
    __syncthreads();
    float inv = 1.f / reds[0];

    for (int i = tid; i < NN; i += 1024) out[i] *= inv;
}

// ---------------- launch: fork CSR-build chain || HMMA GEMM ----------------
extern "C" void kernel_launch(void* const* d_in, const int* in_sizes, int n_in,
                              void* d_out, int out_size)
{
    const int*   ei   = (const int*)  d_in[0];
    const float* ea   = (const float*)d_in[1];
    const float* pe   = (const float*)d_in[2];
    // d_in[3] = sim_w: softmax over one element == 1.0 -> unused
    const float* Wl   = (const float*)d_in[4];
    const float* bl   = (const float*)d_in[5];
    const float* Wr   = (const float*)d_in[6];
    const float* br   = (const float*)d_in[7];
    const float* We   = (const float*)d_in[8];
    const float* att  = (const float*)d_in[9];
    const float* bgn  = (const float*)d_in[10];
    const float* Wout = (const float*)d_in[11];
    const float* bout = (const float*)d_in[12];
    float* out = (float*)d_out;

    static cudaStream_t s1 = nullptr;
    static cudaEvent_t evr = nullptr, evg = nullptr;
    if (s1 == nullptr) {
        cudaStreamCreateWithFlags(&s1, cudaStreamNonBlocking);
        cudaEventCreateWithFlags(&evr, cudaEventDisableTiming);
        cudaEventCreateWithFlags(&evg, cudaEventDisableTiming);
        cudaFuncSetAttribute(k_gemm_mma, cudaFuncAttributeMaxDynamicSharedMemorySize, SM_TOT);
    }

    void* p_cnt = nullptr;
    cudaGetSymbolAddress(&p_cnt, g_cnt);

    // fork: GEMM on s1, CSR build on default stream
    cudaEventRecord(evr, 0);
    cudaStreamWaitEvent(s1, evr, 0);
    k_gemm_mma<<<dim3(GEMM_BX, 2), 256, SM_TOT, s1>>>(pe, Wl, bl, Wr, br);
    cudaEventRecord(evg, s1);

    cudaMemsetAsync(p_cnt, 0, NN * sizeof(int), 0);
    k_hist<<<HIST_BLOCKS, 256>>>(ei);
    k_scan<<<1, 1024>>>();
    k_scatter<<<HIST_BLOCKS, 256>>>(ei, ea);

    // join: aggregation needs both xl/xr and the CSR
    cudaStreamWaitEvent(0, evg, 0);
    k_agg<<<(NN * 32 + 127) / 128, 128>>>(We, att, bgn, Wout, bout);
    k_softmax<<<1, 1024>>>(out);
}